// round 13
// baseline (speedup 1.0000x reference)
#include <cuda_runtime.h>
#include <cuda_bf16.h>
#include <cstdint>

#define B_   2
#define S_   2048
#define T_   4096          // B*S
#define DIM_ 512
#define INNER_ 1024
#define I2_  2048
#define NH_  16
#define DH_  64
#define KSZ_ 4
#define EPS_ 5e-5f
#define NORM_EPS_ 1e-6f
#define CAP_ 15.0f
#define IFSPLIT 16

// ---------------- scratch (device globals; no allocation allowed) ----------
__device__ float g_xinner[T_ * I2_];
__device__ float g_xconv [T_ * INNER_];
__device__ float g_q     [T_ * INNER_];   // fp32 (ifgate)
__device__ float g_k     [T_ * INNER_];
__device__ float g_v     [T_ * INNER_];
__device__ float g_qt    [T_ * INNER_];   // tf32-rounded (attention)
__device__ float g_kt    [T_ * INNER_];
__device__ float g_vt    [T_ * INNER_];
__device__ float g_ifpart[IFSPLIT * T_ * 32];
__device__ float g_if    [T_ * 32];
__device__ float g_gv    [B_ * NH_ * S_];
__device__ float g_Mv    [B_ * NH_ * S_];
__device__ float g_env   [B_ * NH_ * S_];
__device__ float g_hout  [T_ * INNER_];

// ---------------- tf32 mma helpers -----------------------------------------
__device__ __forceinline__ float tfstore(float x) {
    uint32_t r; asm("cvt.rna.tf32.f32 %0, %1;" : "=r"(r) : "f"(x));
    return __uint_as_float(r);
}
__device__ __forceinline__ void mma8(float* c, const uint32_t* a,
                                     uint32_t b0, uint32_t b1) {
    asm volatile(
        "mma.sync.aligned.m16n8k8.row.col.f32.tf32.tf32.f32 "
        "{%0,%1,%2,%3}, {%4,%5,%6,%7}, {%8,%9}, {%0,%1,%2,%3};"
        : "+f"(c[0]), "+f"(c[1]), "+f"(c[2]), "+f"(c[3])
        : "r"(a[0]), "r"(a[1]), "r"(a[2]), "r"(a[3]), "r"(b0), "r"(b1));
}

__device__ __forceinline__ float silu_f(float z) {
    return z / (1.f + __expf(-z));
}

// ---------------- tf32 NT GEMM, software-pipelined (BN=128) -----------------
__global__ __launch_bounds__(256) void gemm_nt_tf32(
    const float* __restrict__ A, const float* __restrict__ Bm,
    float* __restrict__ C, int M, int N, int K)
{
    __shared__ float As[16][136];
    __shared__ float Bs[16][136];
    int bm = blockIdx.y * 128, bn = blockIdx.x * 128;
    int tid = threadIdx.x;
    int warp = tid >> 5, lane = tid & 31;
    int wm = warp & 3;
    int wn = warp >> 2;
    int g = lane >> 2, tig = lane & 3;
    float acc[2][8][4];
#pragma unroll
    for (int mt = 0; mt < 2; mt++)
#pragma unroll
        for (int nt = 0; nt < 8; nt++)
#pragma unroll
            for (int i = 0; i < 4; i++) acc[mt][nt][i] = 0.f;

    int r = tid >> 1, ks = (tid & 1) * 8;
    const float* Ag = A + (long)(bm + r) * K + ks;
    const float* Bg = Bm + (long)(bn + r) * K + ks;

    float4 av0 = *(const float4*)(Ag);
    float4 av1 = *(const float4*)(Ag + 4);
    float4 bv0 = *(const float4*)(Bg);
    float4 bv1 = *(const float4*)(Bg + 4);

    for (int k0 = 0; k0 < K; k0 += 16) {
        __syncthreads();
        As[ks + 0][r] = tfstore(av0.x); As[ks + 1][r] = tfstore(av0.y);
        As[ks + 2][r] = tfstore(av0.z); As[ks + 3][r] = tfstore(av0.w);
        As[ks + 4][r] = tfstore(av1.x); As[ks + 5][r] = tfstore(av1.y);
        As[ks + 6][r] = tfstore(av1.z); As[ks + 7][r] = tfstore(av1.w);
        Bs[ks + 0][r] = tfstore(bv0.x); Bs[ks + 1][r] = tfstore(bv0.y);
        Bs[ks + 2][r] = tfstore(bv0.z); Bs[ks + 3][r] = tfstore(bv0.w);
        Bs[ks + 4][r] = tfstore(bv1.x); Bs[ks + 5][r] = tfstore(bv1.y);
        Bs[ks + 6][r] = tfstore(bv1.z); Bs[ks + 7][r] = tfstore(bv1.w);
        __syncthreads();
        if (k0 + 16 < K) {
            av0 = *(const float4*)(Ag + k0 + 16);
            av1 = *(const float4*)(Ag + k0 + 20);
            bv0 = *(const float4*)(Bg + k0 + 16);
            bv1 = *(const float4*)(Bg + k0 + 20);
        }
#pragma unroll
        for (int kk = 0; kk < 16; kk += 8) {
            uint32_t af[2][4];
#pragma unroll
            for (int mt = 0; mt < 2; mt++) {
                int row = wm * 32 + mt * 16;
                af[mt][0] = __float_as_uint(As[kk + tig][row + g]);
                af[mt][1] = __float_as_uint(As[kk + tig][row + g + 8]);
                af[mt][2] = __float_as_uint(As[kk + tig + 4][row + g]);
                af[mt][3] = __float_as_uint(As[kk + tig + 4][row + g + 8]);
            }
#pragma unroll
            for (int nt = 0; nt < 8; nt++) {
                int col = wn * 64 + nt * 8 + g;
                uint32_t b0 = __float_as_uint(Bs[kk + tig][col]);
                uint32_t b1 = __float_as_uint(Bs[kk + tig + 4][col]);
                mma8(acc[0][nt], af[0], b0, b1);
                mma8(acc[1][nt], af[1], b0, b1);
            }
        }
    }
#pragma unroll
    for (int mt = 0; mt < 2; mt++)
#pragma unroll
        for (int nt = 0; nt < 8; nt++) {
            int row = bm + wm * 32 + mt * 16 + g;
            int col = bn + wn * 64 + nt * 8 + tig * 2;
            C[(long)row * N + col]       = acc[mt][nt][0];
            C[(long)row * N + col + 1]   = acc[mt][nt][1];
            C[(long)(row + 8) * N + col]     = acc[mt][nt][2];
            C[(long)(row + 8) * N + col + 1] = acc[mt][nt][3];
        }
}

// ---------------- causal conv1d (KSZ=4) + SiLU, float4 ----------------------
__global__ __launch_bounds__(256) void conv_silu_kernel(
    const float* __restrict__ xinner, const float* __restrict__ cw,
    const float* __restrict__ cb, float* __restrict__ xconv)
{
    int idx4 = blockIdx.x * 256 + threadIdx.x;
    int c4 = (idx4 & 255) * 4;
    int token = idx4 >> 8;
    int s = token & (S_ - 1);
    int b = token >> 11;
    float4 w0 = *(const float4*)&cw[(c4 + 0) * KSZ_];
    float4 w1 = *(const float4*)&cw[(c4 + 1) * KSZ_];
    float4 w2 = *(const float4*)&cw[(c4 + 2) * KSZ_];
    float4 w3 = *(const float4*)&cw[(c4 + 3) * KSZ_];
    float4 bv = *(const float4*)&cb[c4];
    float a0 = bv.x, a1 = bv.y, a2 = bv.z, a3 = bv.w;
    const float* wj0 = (const float*)&w0;
    const float* wj1 = (const float*)&w1;
    const float* wj2 = (const float*)&w2;
    const float* wj3 = (const float*)&w3;
#pragma unroll
    for (int j = 0; j < KSZ_; j++) {
        int sp = s - (KSZ_ - 1) + j;
        if (sp >= 0) {
            float4 xv = *(const float4*)&xinner[(long)(b * S_ + sp) * I2_ + c4];
            a0 += xv.x * wj0[j];
            a1 += xv.y * wj1[j];
            a2 += xv.z * wj2[j];
            a3 += xv.w * wj3[j];
        }
    }
    float4 o;
    o.x = silu_f(a0); o.y = silu_f(a1); o.z = silu_f(a2); o.w = silu_f(a3);
    *(float4*)&xconv[(long)token * INNER_ + c4] = o;
}

// ---------------- per-head projections + tf32 shadow copies -----------------
__global__ __launch_bounds__(256) void qkv_kernel(
    const float* __restrict__ xconv, const float* __restrict__ xinner,
    const float* __restrict__ Wq, const float* __restrict__ Wk,
    const float* __restrict__ Wv,
    float* __restrict__ q, float* __restrict__ k, float* __restrict__ v,
    float* __restrict__ qt, float* __restrict__ kt, float* __restrict__ vt)
{
    int tt = blockIdx.x;
    int h  = blockIdx.y;
    int z  = blockIdx.z;

    extern __shared__ float dsm[];
    float* Xs = dsm;             // [64][68]
    float* Wa = Xs + 64 * 68;    // [64][68]
    float* Wb = Wa + 64 * 68;    // [64][68] (z=0 only)

    const float* src = z ? xinner : xconv;
    int srcStride = z ? I2_ : INNER_;
    const float* W1 = z ? Wv : Wq;

    int tid = threadIdx.x, tx = tid & 15, ty = tid >> 4;
    int tok0 = tt * 64;
#pragma unroll
    for (int i = 0; i < 4; i++) {
        int c = tid + i * 256;
        int s = c >> 4, d0 = (c & 15) * 4;
        float4 xv = *(const float4*)&src[(long)(tok0 + s) * srcStride + h * DH_ + d0];
        float4 wv = *(const float4*)&W1[h * DH_ * DH_ + s * DH_ + d0];
        Xs[(d0 + 0) * 68 + s] = xv.x; Xs[(d0 + 1) * 68 + s] = xv.y;
        Xs[(d0 + 2) * 68 + s] = xv.z; Xs[(d0 + 3) * 68 + s] = xv.w;
        Wa[(d0 + 0) * 68 + s] = wv.x; Wa[(d0 + 1) * 68 + s] = wv.y;
        Wa[(d0 + 2) * 68 + s] = wv.z; Wa[(d0 + 3) * 68 + s] = wv.w;
        if (z == 0) {
            float4 wk = *(const float4*)&Wk[h * DH_ * DH_ + s * DH_ + d0];
            Wb[(d0 + 0) * 68 + s] = wk.x; Wb[(d0 + 1) * 68 + s] = wk.y;
            Wb[(d0 + 2) * 68 + s] = wk.z; Wb[(d0 + 3) * 68 + s] = wk.w;
        }
    }
    __syncthreads();

    if (z == 0) {
        float accq[4][4], acck[4][4];
#pragma unroll
        for (int i = 0; i < 4; i++)
#pragma unroll
            for (int j = 0; j < 4; j++) { accq[i][j] = 0.f; acck[i][j] = 0.f; }
#pragma unroll 8
        for (int d = 0; d < 64; d++) {
            float4 a = *(const float4*)&Xs[d * 68 + ty * 4];
            float4 bq = *(const float4*)&Wa[d * 68 + tx * 4];
            float4 bk = *(const float4*)&Wb[d * 68 + tx * 4];
            float av[4] = {a.x,a.y,a.z,a.w};
            float bqv[4] = {bq.x,bq.y,bq.z,bq.w};
            float bkv[4] = {bk.x,bk.y,bk.z,bk.w};
#pragma unroll
            for (int i = 0; i < 4; i++)
#pragma unroll
                for (int j = 0; j < 4; j++) {
                    accq[i][j] += av[i] * bqv[j];
                    acck[i][j] += av[i] * bkv[j];
                }
        }
#pragma unroll
        for (int i = 0; i < 4; i++) {
            float4 oq = {accq[i][0],accq[i][1],accq[i][2],accq[i][3]};
            float4 ok = {acck[i][0],acck[i][1],acck[i][2],acck[i][3]};
            long off = (long)(tok0 + ty * 4 + i) * INNER_ + h * DH_ + tx * 4;
            *(float4*)&q[off] = oq;
            *(float4*)&k[off] = ok;
            float4 oqt = {tfstore(oq.x), tfstore(oq.y), tfstore(oq.z), tfstore(oq.w)};
            float4 okt = {tfstore(ok.x), tfstore(ok.y), tfstore(ok.z), tfstore(ok.w)};
            *(float4*)&qt[off] = oqt;
            *(float4*)&kt[off] = okt;
        }
    } else {
        float accv[4][4];
#pragma unroll
        for (int i = 0; i < 4; i++)
#pragma unroll
            for (int j = 0; j < 4; j++) accv[i][j] = 0.f;
#pragma unroll 16
        for (int d = 0; d < 64; d++) {
            float4 a = *(const float4*)&Xs[d * 68 + ty * 4];
            float4 b = *(const float4*)&Wa[d * 68 + tx * 4];
            float av[4] = {a.x,a.y,a.z,a.w};
            float bv[4] = {b.x,b.y,b.z,b.w};
#pragma unroll
            for (int i = 0; i < 4; i++)
#pragma unroll
                for (int j = 0; j < 4; j++) accv[i][j] += av[i] * bv[j];
        }
#pragma unroll
        for (int i = 0; i < 4; i++) {
            float4 o = {accv[i][0],accv[i][1],accv[i][2],accv[i][3]};
            long off = (long)(tok0 + ty * 4 + i) * INNER_ + h * DH_ + tx * 4;
            *(float4*)&v[off] = o;
            float4 ot = {tfstore(o.x), tfstore(o.y), tfstore(o.z), tfstore(o.w)};
            *(float4*)&vt[off] = ot;
        }
    }
}

// ---------------- i/f gate GEMM, split-K partials (widened 4x4) -------------
__global__ __launch_bounds__(256) void ifgate_partial_kernel(
    const float* __restrict__ q, const float* __restrict__ k,
    const float* __restrict__ v, const float* __restrict__ Wif,
    float* __restrict__ part)
{
    int tt = blockIdx.x;
    int z  = blockIdx.y;
    __shared__ float As[32][132];
    __shared__ float Ws[32][36];
    int tid = threadIdx.x;
    int ty = tid >> 3;
    int tx = tid & 7;
    int tok0 = tt * 128;
    float acc[4][4];
#pragma unroll
    for (int i = 0; i < 4; i++)
#pragma unroll
        for (int j = 0; j < 4; j++) acc[i][j] = 0.f;

    int c0 = z * 6;
    for (int cc = 0; cc < 6; cc++) {
        int e0 = (c0 + cc) * 32;
        const float* src = (e0 < 1024) ? q : (e0 < 2048) ? k : v;
        int ec = e0 & 1023;
        __syncthreads();
#pragma unroll
        for (int i = 0; i < 4; i++) {
            int c = tid + i * 256;
            int s = c >> 3, e4 = (c & 7) * 4;
            float4 xv = *(const float4*)&src[(long)(tok0 + s) * INNER_ + ec + e4];
            As[e4 + 0][s] = xv.x; As[e4 + 1][s] = xv.y;
            As[e4 + 2][s] = xv.z; As[e4 + 3][s] = xv.w;
        }
        {
            int gg2 = tid >> 3, e4 = (tid & 7) * 4;
            float4 wv = *(const float4*)&Wif[(long)gg2 * 3072 + e0 + e4];
            Ws[e4 + 0][gg2] = wv.x; Ws[e4 + 1][gg2] = wv.y;
            Ws[e4 + 2][gg2] = wv.z; Ws[e4 + 3][gg2] = wv.w;
        }
        __syncthreads();
#pragma unroll 8
        for (int e = 0; e < 32; e++) {
            float4 a = *(const float4*)&As[e][ty * 4];
            float4 b = *(const float4*)&Ws[e][tx * 4];
            float av[4] = {a.x,a.y,a.z,a.w};
            float bv[4] = {b.x,b.y,b.z,b.w};
#pragma unroll
            for (int i = 0; i < 4; i++)
#pragma unroll
                for (int j = 0; j < 4; j++) acc[i][j] += av[i] * bv[j];
        }
    }
#pragma unroll
    for (int i = 0; i < 4; i++) {
        int token = tok0 + ty * 4 + i;
        float4 o = {acc[i][0],acc[i][1],acc[i][2],acc[i][3]};
        *(float4*)&part[((long)z * T_ + token) * 32 + tx * 4] = o;
    }
}

// ---------------- split-K reduce + bias + cap (float4) ----------------------
__global__ __launch_bounds__(256) void ifreduce_kernel(
    const float* __restrict__ part, const float* __restrict__ bif,
    float* __restrict__ ifp)
{
    int idx4 = blockIdx.x * 256 + threadIdx.x;
    int base = idx4 * 4;
    int g4 = base & 31;
    float4 s = {0.f, 0.f, 0.f, 0.f};
#pragma unroll
    for (int z = 0; z < IFSPLIT; z++) {
        float4 p = *(const float4*)&part[(long)z * T_ * 32 + base];
        s.x += p.x; s.y += p.y; s.z += p.z; s.w += p.w;
    }
    float4 bb = *(const float4*)&bif[g4];
    float4 o;
    o.x = CAP_ * tanhf((s.x + bb.x) * (1.0f / CAP_));
    o.y = CAP_ * tanhf((s.y + bb.y) * (1.0f / CAP_));
    o.z = CAP_ * tanhf((s.z + bb.z) * (1.0f / CAP_));
    o.w = CAP_ * tanhf((s.w + bb.w) * (1.0f / CAP_));
    *(float4*)&ifp[base] = o;
}

// ---------------- gate prefix scan per (b,h) --------------------------------
__global__ __launch_bounds__(256) void gate_scan_kernel(
    const float* __restrict__ ifp, float* __restrict__ gg,
    float* __restrict__ gM, float* __restrict__ gEn)
{
    const float NEGINF = -3.0e38f;
    int bh = blockIdx.x;
    int b = bh / NH_, h = bh % NH_;
    int tid = threadIdx.x;
    __shared__ float sbuf[256];
    const int VPT = 8;
    float li[VPT], cs[VPT];
    float csum = 0.f;
#pragma unroll
    for (int j = 0; j < VPT; j++) {
        int s = tid * VPT + j;
        long base = (long)(b * S_ + s) * 32;
        float f = ifp[base + 16 + h];
        li[j] = ifp[base + h];
        float ls = fminf(f, 0.f) - log1pf(__expf(-fabsf(f)));
        csum += ls;
        cs[j] = csum;
    }
    sbuf[tid] = csum; __syncthreads();
    for (int off = 1; off < 256; off <<= 1) {
        float vv = (tid >= off) ? sbuf[tid - off] : 0.f;
        __syncthreads();
        sbuf[tid] += vv;
        __syncthreads();
    }
    float excl = sbuf[tid] - csum;
    float Fc[VPT], gv[VPT], mcs[VPT];
    float mx = NEGINF;
#pragma unroll
    for (int j = 0; j < VPT; j++) {
        Fc[j] = excl + cs[j];
        gv[j] = li[j] - Fc[j];
        mx = fmaxf(mx, gv[j]);
        mcs[j] = mx;
    }
    __syncthreads();
    sbuf[tid] = mx; __syncthreads();
    for (int off = 1; off < 256; off <<= 1) {
        float vv = (tid >= off) ? sbuf[tid - off] : NEGINF;
        __syncthreads();
        sbuf[tid] = fmaxf(sbuf[tid], vv);
        __syncthreads();
    }
    float emax = (tid == 0) ? NEGINF : sbuf[tid - 1];
#pragma unroll
    for (int j = 0; j < VPT; j++) {
        int s = tid * VPT + j;
        long o = (long)bh * S_ + s;
        float M = fmaxf(emax, mcs[j]);
        gg[o] = gv[j];
        gM[o] = M;
        gEn[o] = __expf(-(Fc[j] + M));
    }
}

// ---------------- mLSTM attention (tf32 mma, pre-converted inputs) ----------
#define VSTR 88
__global__ __launch_bounds__(256) void mlstm_attn_tf32(
    const float* __restrict__ q, const float* __restrict__ k,
    const float* __restrict__ v, const float* __restrict__ gg,
    const float* __restrict__ gM, const float* __restrict__ gEn,
    const float* __restrict__ xinner, const float* __restrict__ xconv,
    const float* __restrict__ norm_w, const float* __restrict__ skip,
    float* __restrict__ hout)
{
    int bh = blockIdx.y;
    int b = bh >> 4, h = bh & 15;
    extern __shared__ float sm[];
    float* Qs  = sm;                 // [64][68] s-major
    float* Ks  = Qs + 64 * 68;       // [64][68] t-major; later H[s][d]
    float* Ps  = Ks + 64 * 68;       // [64][68] s-major
    float* Vs  = Ps + 64 * 68;       // [64][VSTR] t-major (col 64 = ones)
    float* Msv = Vs + 64 * VSTR;     // [64]
    float* esv = Msv + 64;           // [64]  exp(g[t] - Mend)
    float* rsv = esv + 64;           // [64]

    int tid = threadIdx.x;
    int warp = tid >> 5, lane = tid & 31;
    int wm = warp & 3, wn = warp >> 2;
    int g = lane >> 2, tig = lane & 3;
    int srow0 = wm * 16 + g, srow1 = srow0 + 8;

    for (int i = tid; i < 64 * (VSTR - 64); i += 256) {
        int t = i / (VSTR - 64), c = i % (VSTR - 64);
        Vs[t * VSTR + 64 + c] = (c == 0) ? 1.0f : 0.0f;
    }

    for (int rep = 0; rep < 2; rep++) {
        int qt = rep ? (31 - (int)blockIdx.x) : (int)blockIdx.x;
        int tok0 = b * S_ + qt * 64;

        __syncthreads();
#pragma unroll
        for (int i = 0; i < 4; i++) {
            int c = tid + i * 256; int s = c >> 4, d0 = (c & 15) * 4;
            float4 qv = *(const float4*)&q[(long)(tok0 + s) * INNER_ + h * DH_ + d0];
            *(float4*)&Qs[s * 68 + d0] = qv;
        }
        if (tid < 64) Msv[tid] = gM[(long)bh * S_ + qt * 64 + tid];
        __syncthreads();
        float Mi0 = Msv[srow0], Mi1 = Msv[srow1];

        uint32_t qf[8][4];
#pragma unroll
        for (int k08 = 0; k08 < 8; k08++) {
            int k0 = k08 * 8;
            qf[k08][0] = __float_as_uint(Qs[srow0 * 68 + k0 + tig]);
            qf[k08][1] = __float_as_uint(Qs[srow1 * 68 + k0 + tig]);
            qf[k08][2] = __float_as_uint(Qs[srow0 * 68 + k0 + tig + 4]);
            qf[k08][3] = __float_as_uint(Qs[srow1 * 68 + k0 + tig + 4]);
        }

        float acc[5][4];
#pragma unroll
        for (int nt = 0; nt < 5; nt++)
#pragma unroll
            for (int i = 0; i < 4; i++) acc[nt][i] = 0.f;

        for (int kt = 0; kt <= qt; kt++) {
            __syncthreads();
            int ktok = b * S_ + kt * 64;
            float Mend = gM[(long)bh * S_ + kt * 64 + 63];
#pragma unroll
            for (int i = 0; i < 4; i++) {
                int c = tid + i * 256; int t = c >> 4, d0 = (c & 15) * 4;
                float4 kv = *(const float4*)&k[(long)(ktok + t) * INNER_ + h * DH_ + d0];
                float4 vv = *(const float4*)&v[(long)(ktok + t) * INNER_ + h * DH_ + d0];
                *(float4*)&Ks[t * 68 + d0] = kv;
                *(float4*)&Vs[t * VSTR + d0] = vv;
            }
            if (tid < 64)
                esv[tid] = __expf(gg[(long)bh * S_ + kt * 64 + tid] - Mend);
            __syncthreads();

            float p[4][4];
#pragma unroll
            for (int nt = 0; nt < 4; nt++)
#pragma unroll
                for (int i = 0; i < 4; i++) p[nt][i] = 0.f;
#pragma unroll
            for (int k08 = 0; k08 < 8; k08++) {
                int k0 = k08 * 8;
#pragma unroll
                for (int nt = 0; nt < 4; nt++) {
                    int t = wn * 32 + nt * 8 + g;
                    uint32_t b0 = __float_as_uint(Ks[t * 68 + k0 + tig]);
                    uint32_t b1 = __float_as_uint(Ks[t * 68 + k0 + tig + 4]);
                    mma8(p[nt], qf[k08], b0, b1);
                }
            }

            float fr0 = 0.125f * __expf(Mend - Mi0);
            float fr1 = 0.125f * __expf(Mend - Mi1);
            bool diag = (kt == qt);
#pragma unroll
            for (int nt = 0; nt < 4; nt++) {
                int c0c = wn * 32 + nt * 8 + tig * 2;
                float ev0 = esv[c0c], ev1 = esv[c0c + 1];
                float e00 = (diag && c0c     > srow0) ? 0.f : p[nt][0] * fr0 * ev0;
                float e01 = (diag && c0c + 1 > srow0) ? 0.f : p[nt][1] * fr0 * ev1;
                float e10 = (diag && c0c     > srow1) ? 0.f : p[nt][2] * fr1 * ev0;
                float e11 = (diag && c0c + 1 > srow1) ? 0.f : p[nt][3] * fr1 * ev1;
                Ps[srow0 * 68 + c0c]     = tfstore(e00);
                Ps[srow0 * 68 + c0c + 1] = tfstore(e01);
                Ps[srow1 * 68 + c0c]     = tfstore(e10);
                Ps[srow1 * 68 + c0c + 1] = tfstore(e11);
            }
            __syncthreads();

#pragma unroll
            for (int k08 = 0; k08 < 8; k08++) {
                int k0 = k08 * 8;
                uint32_t af[4];
                af[0] = __float_as_uint(Ps[srow0 * 68 + k0 + tig]);
                af[1] = __float_as_uint(Ps[srow1 * 68 + k0 + tig]);
                af[2] = __float_as_uint(Ps[srow0 * 68 + k0 + tig + 4]);
                af[3] = __float_as_uint(Ps[srow1 * 68 + k0 + tig + 4]);
#pragma unroll
                for (int nt = 0; nt < 5; nt++) {
                    int d = wn * 40 + nt * 8 + g;
                    uint32_t b0 = __float_as_uint(Vs[(k0 + tig) * VSTR + d]);
                    uint32_t b1 = __float_as_uint(Vs[(k0 + tig + 4) * VSTR + d]);
                    mma8(acc[nt], af, b0, b1);
                }
            }
        }
        __syncthreads();

#pragma unroll
        for (int nt = 0; nt < 5; nt++) {
            int dcol = wn * 40 + nt * 8 + tig * 2;
            if (dcol < 64) {
                Ks[srow0 * 68 + dcol]     = acc[nt][0];
                Ks[srow0 * 68 + dcol + 1] = acc[nt][1];
                Ks[srow1 * 68 + dcol]     = acc[nt][2];
                Ks[srow1 * 68 + dcol + 1] = acc[nt][3];
            } else if (dcol == 64) {
                rsv[srow0] = acc[nt][0];
                rsv[srow1] = acc[nt][2];
            }
        }
        __syncthreads();

        // epilogue (vectorized global traffic)
        int r2 = tid >> 2, qd = tid & 3;
        float n = fmaxf(fabsf(rsv[r2]), gEn[(long)bh * S_ + qt * 64 + r2]);
        float inv = 1.f / (n + EPS_);
        float hv[16];
        float ss = 0.f;
#pragma unroll
        for (int u = 0; u < 16; u++) {
            hv[u] = Ks[r2 * 68 + qd * 16 + u] * inv;
            ss += hv[u] * hv[u];
        }
        Qs[r2 * 4 + qd] = ss;
        __syncthreads();
        float sumsq = Qs[r2 * 4 + 0] + Qs[r2 * 4 + 1] + Qs[r2 * 4 + 2] + Qs[r2 * 4 + 3];
        float rrms = rsqrtf(sumsq * (1.f / 64.f) + NORM_EPS_);
        int token = tok0 + r2;
        int cbase = h * DH_ + qd * 16;
#pragma unroll
        for (int u4 = 0; u4 < 4; u4++) {
            int c = cbase + u4 * 4;
            float4 nw = *(const float4*)&norm_w[c];
            float4 sk = *(const float4*)&skip[c];
            float4 xc = *(const float4*)&xconv[(long)token * INNER_ + c];
            float4 zz = *(const float4*)&xinner[(long)token * I2_ + INNER_ + c];
            float4 o;
            o.x = (hv[u4*4+0] * rrms * (1.f + nw.x) + sk.x * xc.x) * silu_f(zz.x);
            o.y = (hv[u4*4+1] * rrms * (1.f + nw.y) + sk.y * xc.y) * silu_f(zz.y);
            o.z = (hv[u4*4+2] * rrms * (1.f + nw.z) + sk.z * xc.z) * silu_f(zz.z);
            o.w = (hv[u4*4+3] * rrms * (1.f + nw.w) + sk.w * xc.w) * silu_f(zz.w);
            *(float4*)&hout[(long)token * INNER_ + c] = o;
        }
    }
}

// ---------------------------------------------------------------------------
extern "C" void kernel_launch(void* const* d_in, const int* in_sizes, int n_in,
                              void* d_out, int out_size)
{
    const float* x      = (const float*)d_in[0];
    const float* W_up   = (const float*)d_in[1];
    const float* W_q    = (const float*)d_in[2];
    const float* W_k    = (const float*)d_in[3];
    const float* W_v    = (const float*)d_in[4];
    const float* conv_w = (const float*)d_in[5];
    const float* conv_b = (const float*)d_in[6];
    const float* W_if   = (const float*)d_in[7];
    const float* b_if   = (const float*)d_in[8];
    const float* norm_w = (const float*)d_in[9];
    const float* skip   = (const float*)d_in[10];
    const float* W_down = (const float*)d_in[11];
    float* out = (float*)d_out;

    float *xinner, *xconv, *qp, *kp, *vp, *qtp, *ktp, *vtp;
    float *ifpart, *ifp, *gv, *Mv, *env, *hout;
    cudaGetSymbolAddress((void**)&xinner, g_xinner);
    cudaGetSymbolAddress((void**)&xconv,  g_xconv);
    cudaGetSymbolAddress((void**)&qp,     g_q);
    cudaGetSymbolAddress((void**)&kp,     g_k);
    cudaGetSymbolAddress((void**)&vp,     g_v);
    cudaGetSymbolAddress((void**)&qtp,    g_qt);
    cudaGetSymbolAddress((void**)&ktp,    g_kt);
    cudaGetSymbolAddress((void**)&vtp,    g_vt);
    cudaGetSymbolAddress((void**)&ifpart, g_ifpart);
    cudaGetSymbolAddress((void**)&ifp,    g_if);
    cudaGetSymbolAddress((void**)&gv,     g_gv);
    cudaGetSymbolAddress((void**)&Mv,     g_Mv);
    cudaGetSymbolAddress((void**)&env,    g_env);
    cudaGetSymbolAddress((void**)&hout,   g_hout);

    const int ATTN_SMEM = (3 * 64 * 68 + 64 * VSTR + 192) * (int)sizeof(float);
    cudaFuncSetAttribute(mlstm_attn_tf32,
                         cudaFuncAttributeMaxDynamicSharedMemorySize, ATTN_SMEM);
    const int QKV_SMEM = 3 * 64 * 68 * (int)sizeof(float);
    cudaFuncSetAttribute(qkv_kernel,
                         cudaFuncAttributeMaxDynamicSharedMemorySize, QKV_SMEM);

    gemm_nt_tf32<<<dim3(I2_ / 128, T_ / 128), 256>>>(x, W_up, xinner, T_, I2_, DIM_);
    conv_silu_kernel<<<(T_ * INNER_ / 4) / 256, 256>>>(xinner, conv_w, conv_b, xconv);
    qkv_kernel<<<dim3(T_ / 64, NH_, 2), 256, QKV_SMEM>>>(
        xconv, xinner, W_q, W_k, W_v, qp, kp, vp, qtp, ktp, vtp);
    ifgate_partial_kernel<<<dim3(T_ / 128, IFSPLIT), 256>>>(qp, kp, vp, W_if, ifpart);
    ifreduce_kernel<<<(T_ * 32 / 4) / 256, 256>>>(ifpart, b_if, ifp);
    gate_scan_kernel<<<B_ * NH_, 256>>>(ifp, gv, Mv, env);
    mlstm_attn_tf32<<<dim3(S_ / 128, B_ * NH_), 256, ATTN_SMEM>>>(
        qtp, ktp, vtp, gv, Mv, env, xinner, xconv, norm_w, skip, hout);
    gemm_nt_tf32<<<dim3(DIM_ / 128, T_ / 128), 256>>>(hout, W_down, out, T_, DIM_, INNER_);
}

// round 14
// speedup vs baseline: 1.0329x; 1.0329x over previous
#include <cuda_runtime.h>
#include <cuda_bf16.h>
#include <cstdint>

#define B_   2
#define S_   2048
#define T_   4096          // B*S
#define DIM_ 512
#define INNER_ 1024
#define I2_  2048
#define NH_  16
#define DH_  64
#define KSZ_ 4
#define EPS_ 5e-5f
#define NORM_EPS_ 1e-6f
#define CAP_ 15.0f
#define IFSPLIT 16

// ---------------- scratch (device globals; no allocation allowed) ----------
__device__ float g_xinner[T_ * I2_];
__device__ float g_xconv [T_ * INNER_];
__device__ float g_q     [T_ * INNER_];
__device__ float g_k     [T_ * INNER_];
__device__ float g_v     [T_ * INNER_];
__device__ float g_ifpart[IFSPLIT * T_ * 32];
__device__ float g_if    [T_ * 32];
__device__ float g_gv    [B_ * NH_ * S_];
__device__ float g_Mv    [B_ * NH_ * S_];
__device__ float g_env   [B_ * NH_ * S_];
__device__ float g_hout  [T_ * INNER_];

// ---------------- tf32 mma helpers -----------------------------------------
__device__ __forceinline__ float tfstore(float x) {
    uint32_t r; asm("cvt.rna.tf32.f32 %0, %1;" : "=r"(r) : "f"(x));
    return __uint_as_float(r);
}
__device__ __forceinline__ void mma8(float* c, const uint32_t* a,
                                     uint32_t b0, uint32_t b1) {
    asm volatile(
        "mma.sync.aligned.m16n8k8.row.col.f32.tf32.tf32.f32 "
        "{%0,%1,%2,%3}, {%4,%5,%6,%7}, {%8,%9}, {%0,%1,%2,%3};"
        : "+f"(c[0]), "+f"(c[1]), "+f"(c[2]), "+f"(c[3])
        : "r"(a[0]), "r"(a[1]), "r"(a[2]), "r"(a[3]), "r"(b0), "r"(b1));
}

__device__ __forceinline__ float silu_f(float z) {
    return z / (1.f + __expf(-z));
}

// ---------------- tf32 NT GEMM, software-pipelined (BN=128) -----------------
__global__ __launch_bounds__(256) void gemm_nt_tf32(
    const float* __restrict__ A, const float* __restrict__ Bm,
    float* __restrict__ C, int M, int N, int K)
{
    __shared__ float As[16][136];
    __shared__ float Bs[16][136];
    int bm = blockIdx.y * 128, bn = blockIdx.x * 128;
    int tid = threadIdx.x;
    int warp = tid >> 5, lane = tid & 31;
    int wm = warp & 3;
    int wn = warp >> 2;
    int g = lane >> 2, tig = lane & 3;
    float acc[2][8][4];
#pragma unroll
    for (int mt = 0; mt < 2; mt++)
#pragma unroll
        for (int nt = 0; nt < 8; nt++)
#pragma unroll
            for (int i = 0; i < 4; i++) acc[mt][nt][i] = 0.f;

    int r = tid >> 1, ks = (tid & 1) * 8;
    const float* Ag = A + (long)(bm + r) * K + ks;
    const float* Bg = Bm + (long)(bn + r) * K + ks;

    float4 av0 = *(const float4*)(Ag);
    float4 av1 = *(const float4*)(Ag + 4);
    float4 bv0 = *(const float4*)(Bg);
    float4 bv1 = *(const float4*)(Bg + 4);

    for (int k0 = 0; k0 < K; k0 += 16) {
        __syncthreads();
        As[ks + 0][r] = tfstore(av0.x); As[ks + 1][r] = tfstore(av0.y);
        As[ks + 2][r] = tfstore(av0.z); As[ks + 3][r] = tfstore(av0.w);
        As[ks + 4][r] = tfstore(av1.x); As[ks + 5][r] = tfstore(av1.y);
        As[ks + 6][r] = tfstore(av1.z); As[ks + 7][r] = tfstore(av1.w);
        Bs[ks + 0][r] = tfstore(bv0.x); Bs[ks + 1][r] = tfstore(bv0.y);
        Bs[ks + 2][r] = tfstore(bv0.z); Bs[ks + 3][r] = tfstore(bv0.w);
        Bs[ks + 4][r] = tfstore(bv1.x); Bs[ks + 5][r] = tfstore(bv1.y);
        Bs[ks + 6][r] = tfstore(bv1.z); Bs[ks + 7][r] = tfstore(bv1.w);
        __syncthreads();
        if (k0 + 16 < K) {
            av0 = *(const float4*)(Ag + k0 + 16);
            av1 = *(const float4*)(Ag + k0 + 20);
            bv0 = *(const float4*)(Bg + k0 + 16);
            bv1 = *(const float4*)(Bg + k0 + 20);
        }
#pragma unroll
        for (int kk = 0; kk < 16; kk += 8) {
            uint32_t af[2][4];
#pragma unroll
            for (int mt = 0; mt < 2; mt++) {
                int row = wm * 32 + mt * 16;
                af[mt][0] = __float_as_uint(As[kk + tig][row + g]);
                af[mt][1] = __float_as_uint(As[kk + tig][row + g + 8]);
                af[mt][2] = __float_as_uint(As[kk + tig + 4][row + g]);
                af[mt][3] = __float_as_uint(As[kk + tig + 4][row + g + 8]);
            }
#pragma unroll
            for (int nt = 0; nt < 8; nt++) {
                int col = wn * 64 + nt * 8 + g;
                uint32_t b0 = __float_as_uint(Bs[kk + tig][col]);
                uint32_t b1 = __float_as_uint(Bs[kk + tig + 4][col]);
                mma8(acc[0][nt], af[0], b0, b1);
                mma8(acc[1][nt], af[1], b0, b1);
            }
        }
    }
#pragma unroll
    for (int mt = 0; mt < 2; mt++)
#pragma unroll
        for (int nt = 0; nt < 8; nt++) {
            int row = bm + wm * 32 + mt * 16 + g;
            int col = bn + wn * 64 + nt * 8 + tig * 2;
            C[(long)row * N + col]       = acc[mt][nt][0];
            C[(long)row * N + col + 1]   = acc[mt][nt][1];
            C[(long)(row + 8) * N + col]     = acc[mt][nt][2];
            C[(long)(row + 8) * N + col + 1] = acc[mt][nt][3];
        }
}

// ---------------- causal conv1d (KSZ=4) + SiLU, float4, 2 tokens/thread -----
__global__ __launch_bounds__(256) void conv_silu_kernel(
    const float* __restrict__ xinner, const float* __restrict__ cw,
    const float* __restrict__ cb, float* __restrict__ xconv)
{
    // each thread: channel-quad c4, token pair (2*tp, 2*tp+1)
    int idx = blockIdx.x * 256 + threadIdx.x;   // over T_/2 * 256
    int c4 = (idx & 255) * 4;
    int tp = idx >> 8;
    int s0 = (tp << 1) & (S_ - 1);     // even token within sequence
    int b = tp >> 10;                   // tp in [0, 2048): 1024 pairs per batch
    float4 w0 = *(const float4*)&cw[(c4 + 0) * KSZ_];
    float4 w1 = *(const float4*)&cw[(c4 + 1) * KSZ_];
    float4 w2 = *(const float4*)&cw[(c4 + 2) * KSZ_];
    float4 w3 = *(const float4*)&cw[(c4 + 3) * KSZ_];
    float4 bv = *(const float4*)&cb[c4];
    const float* wj0 = (const float*)&w0;
    const float* wj1 = (const float*)&w1;
    const float* wj2 = (const float*)&w2;
    const float* wj3 = (const float*)&w3;

    // taps for both tokens: rows s0-3 .. s0+1 (5 rows)
    float4 xr[5];
#pragma unroll
    for (int r = 0; r < 5; r++) {
        int sp = s0 - 3 + r;
        if (sp >= 0)
            xr[r] = *(const float4*)&xinner[(long)(b * S_ + sp) * I2_ + c4];
        else
            xr[r] = make_float4(0.f, 0.f, 0.f, 0.f);
    }
    long obase = (long)(b * S_ + s0) * INNER_ + c4;
#pragma unroll
    for (int t = 0; t < 2; t++) {
        float a0 = bv.x, a1 = bv.y, a2 = bv.z, a3 = bv.w;
#pragma unroll
        for (int j = 0; j < KSZ_; j++) {
            float4 xv = xr[t + j];
            a0 += xv.x * wj0[j];
            a1 += xv.y * wj1[j];
            a2 += xv.z * wj2[j];
            a3 += xv.w * wj3[j];
        }
        float4 o;
        o.x = silu_f(a0); o.y = silu_f(a1); o.z = silu_f(a2); o.w = silu_f(a3);
        *(float4*)&xconv[obase + (long)t * INNER_] = o;
    }
}

// ---------------- per-head projections: z=0 -> q,k from xconv; z=1 -> v -----
__global__ __launch_bounds__(256) void qkv_kernel(
    const float* __restrict__ xconv, const float* __restrict__ xinner,
    const float* __restrict__ Wq, const float* __restrict__ Wk,
    const float* __restrict__ Wv,
    float* __restrict__ q, float* __restrict__ k, float* __restrict__ v)
{
    int tt = blockIdx.x;
    int h  = blockIdx.y;
    int z  = blockIdx.z;

    extern __shared__ float dsm[];
    float* Xs = dsm;             // [64][68]
    float* Wa = Xs + 64 * 68;    // [64][68]
    float* Wb = Wa + 64 * 68;    // [64][68] (z=0 only)

    const float* src = z ? xinner : xconv;
    int srcStride = z ? I2_ : INNER_;
    const float* W1 = z ? Wv : Wq;

    int tid = threadIdx.x, tx = tid & 15, ty = tid >> 4;
    int tok0 = tt * 64;
#pragma unroll
    for (int i = 0; i < 4; i++) {
        int c = tid + i * 256;
        int s = c >> 4, d0 = (c & 15) * 4;
        float4 xv = *(const float4*)&src[(long)(tok0 + s) * srcStride + h * DH_ + d0];
        float4 wv = *(const float4*)&W1[h * DH_ * DH_ + s * DH_ + d0];
        Xs[(d0 + 0) * 68 + s] = xv.x; Xs[(d0 + 1) * 68 + s] = xv.y;
        Xs[(d0 + 2) * 68 + s] = xv.z; Xs[(d0 + 3) * 68 + s] = xv.w;
        Wa[(d0 + 0) * 68 + s] = wv.x; Wa[(d0 + 1) * 68 + s] = wv.y;
        Wa[(d0 + 2) * 68 + s] = wv.z; Wa[(d0 + 3) * 68 + s] = wv.w;
        if (z == 0) {
            float4 wk = *(const float4*)&Wk[h * DH_ * DH_ + s * DH_ + d0];
            Wb[(d0 + 0) * 68 + s] = wk.x; Wb[(d0 + 1) * 68 + s] = wk.y;
            Wb[(d0 + 2) * 68 + s] = wk.z; Wb[(d0 + 3) * 68 + s] = wk.w;
        }
    }
    __syncthreads();

    if (z == 0) {
        float accq[4][4], acck[4][4];
#pragma unroll
        for (int i = 0; i < 4; i++)
#pragma unroll
            for (int j = 0; j < 4; j++) { accq[i][j] = 0.f; acck[i][j] = 0.f; }
#pragma unroll 8
        for (int d = 0; d < 64; d++) {
            float4 a = *(const float4*)&Xs[d * 68 + ty * 4];
            float4 bq = *(const float4*)&Wa[d * 68 + tx * 4];
            float4 bk = *(const float4*)&Wb[d * 68 + tx * 4];
            float av[4] = {a.x,a.y,a.z,a.w};
            float bqv[4] = {bq.x,bq.y,bq.z,bq.w};
            float bkv[4] = {bk.x,bk.y,bk.z,bk.w};
#pragma unroll
            for (int i = 0; i < 4; i++)
#pragma unroll
                for (int j = 0; j < 4; j++) {
                    accq[i][j] += av[i] * bqv[j];
                    acck[i][j] += av[i] * bkv[j];
                }
        }
#pragma unroll
        for (int i = 0; i < 4; i++) {
            float4 oq = {accq[i][0],accq[i][1],accq[i][2],accq[i][3]};
            float4 ok = {acck[i][0],acck[i][1],acck[i][2],acck[i][3]};
            long off = (long)(tok0 + ty * 4 + i) * INNER_ + h * DH_ + tx * 4;
            *(float4*)&q[off] = oq;
            *(float4*)&k[off] = ok;
        }
    } else {
        float accv[4][4];
#pragma unroll
        for (int i = 0; i < 4; i++)
#pragma unroll
            for (int j = 0; j < 4; j++) accv[i][j] = 0.f;
#pragma unroll 16
        for (int d = 0; d < 64; d++) {
            float4 a = *(const float4*)&Xs[d * 68 + ty * 4];
            float4 b = *(const float4*)&Wa[d * 68 + tx * 4];
            float av[4] = {a.x,a.y,a.z,a.w};
            float bv[4] = {b.x,b.y,b.z,b.w};
#pragma unroll
            for (int i = 0; i < 4; i++)
#pragma unroll
                for (int j = 0; j < 4; j++) accv[i][j] += av[i] * bv[j];
        }
#pragma unroll
        for (int i = 0; i < 4; i++) {
            float4 o = {accv[i][0],accv[i][1],accv[i][2],accv[i][3]};
            *(float4*)&v[(long)(tok0 + ty * 4 + i) * INNER_ + h * DH_ + tx * 4] = o;
        }
    }
}

// ---------------- i/f gate GEMM, split-K partials (widened 4x4) -------------
__global__ __launch_bounds__(256) void ifgate_partial_kernel(
    const float* __restrict__ q, const float* __restrict__ k,
    const float* __restrict__ v, const float* __restrict__ Wif,
    float* __restrict__ part)
{
    int tt = blockIdx.x;
    int z  = blockIdx.y;
    __shared__ float As[32][132];
    __shared__ float Ws[32][36];
    int tid = threadIdx.x;
    int ty = tid >> 3;
    int tx = tid & 7;
    int tok0 = tt * 128;
    float acc[4][4];
#pragma unroll
    for (int i = 0; i < 4; i++)
#pragma unroll
        for (int j = 0; j < 4; j++) acc[i][j] = 0.f;

    int c0 = z * 6;
    for (int cc = 0; cc < 6; cc++) {
        int e0 = (c0 + cc) * 32;
        const float* src = (e0 < 1024) ? q : (e0 < 2048) ? k : v;
        int ec = e0 & 1023;
        __syncthreads();
#pragma unroll
        for (int i = 0; i < 4; i++) {
            int c = tid + i * 256;
            int s = c >> 3, e4 = (c & 7) * 4;
            float4 xv = *(const float4*)&src[(long)(tok0 + s) * INNER_ + ec + e4];
            As[e4 + 0][s] = xv.x; As[e4 + 1][s] = xv.y;
            As[e4 + 2][s] = xv.z; As[e4 + 3][s] = xv.w;
        }
        {
            int gg2 = tid >> 3, e4 = (tid & 7) * 4;
            float4 wv = *(const float4*)&Wif[(long)gg2 * 3072 + e0 + e4];
            Ws[e4 + 0][gg2] = wv.x; Ws[e4 + 1][gg2] = wv.y;
            Ws[e4 + 2][gg2] = wv.z; Ws[e4 + 3][gg2] = wv.w;
        }
        __syncthreads();
#pragma unroll 8
        for (int e = 0; e < 32; e++) {
            float4 a = *(const float4*)&As[e][ty * 4];
            float4 b = *(const float4*)&Ws[e][tx * 4];
            float av[4] = {a.x,a.y,a.z,a.w};
            float bv[4] = {b.x,b.y,b.z,b.w};
#pragma unroll
            for (int i = 0; i < 4; i++)
#pragma unroll
                for (int j = 0; j < 4; j++) acc[i][j] += av[i] * bv[j];
        }
    }
#pragma unroll
    for (int i = 0; i < 4; i++) {
        int token = tok0 + ty * 4 + i;
        float4 o = {acc[i][0],acc[i][1],acc[i][2],acc[i][3]};
        *(float4*)&part[((long)z * T_ + token) * 32 + tx * 4] = o;
    }
}

// ---------------- split-K reduce + bias + cap (float4) ----------------------
__global__ __launch_bounds__(256) void ifreduce_kernel(
    const float* __restrict__ part, const float* __restrict__ bif,
    float* __restrict__ ifp)
{
    int idx4 = blockIdx.x * 256 + threadIdx.x;
    int base = idx4 * 4;
    int g4 = base & 31;
    float4 s = {0.f, 0.f, 0.f, 0.f};
#pragma unroll
    for (int z = 0; z < IFSPLIT; z++) {
        float4 p = *(const float4*)&part[(long)z * T_ * 32 + base];
        s.x += p.x; s.y += p.y; s.z += p.z; s.w += p.w;
    }
    float4 bb = *(const float4*)&bif[g4];
    float4 o;
    o.x = CAP_ * tanhf((s.x + bb.x) * (1.0f / CAP_));
    o.y = CAP_ * tanhf((s.y + bb.y) * (1.0f / CAP_));
    o.z = CAP_ * tanhf((s.z + bb.z) * (1.0f / CAP_));
    o.w = CAP_ * tanhf((s.w + bb.w) * (1.0f / CAP_));
    *(float4*)&ifp[base] = o;
}

// ---------------- gate prefix scan per (b,h) --------------------------------
__global__ __launch_bounds__(256) void gate_scan_kernel(
    const float* __restrict__ ifp, float* __restrict__ gg,
    float* __restrict__ gM, float* __restrict__ gEn)
{
    const float NEGINF = -3.0e38f;
    int bh = blockIdx.x;
    int b = bh / NH_, h = bh % NH_;
    int tid = threadIdx.x;
    __shared__ float sbuf[256];
    const int VPT = 8;
    float li[VPT], cs[VPT];
    float csum = 0.f;
#pragma unroll
    for (int j = 0; j < VPT; j++) {
        int s = tid * VPT + j;
        long base = (long)(b * S_ + s) * 32;
        float f = ifp[base + 16 + h];
        li[j] = ifp[base + h];
        float ls = fminf(f, 0.f) - log1pf(__expf(-fabsf(f)));
        csum += ls;
        cs[j] = csum;
    }
    sbuf[tid] = csum; __syncthreads();
    for (int off = 1; off < 256; off <<= 1) {
        float vv = (tid >= off) ? sbuf[tid - off] : 0.f;
        __syncthreads();
        sbuf[tid] += vv;
        __syncthreads();
    }
    float excl = sbuf[tid] - csum;
    float Fc[VPT], gv[VPT], mcs[VPT];
    float mx = NEGINF;
#pragma unroll
    for (int j = 0; j < VPT; j++) {
        Fc[j] = excl + cs[j];
        gv[j] = li[j] - Fc[j];
        mx = fmaxf(mx, gv[j]);
        mcs[j] = mx;
    }
    __syncthreads();
    sbuf[tid] = mx; __syncthreads();
    for (int off = 1; off < 256; off <<= 1) {
        float vv = (tid >= off) ? sbuf[tid - off] : NEGINF;
        __syncthreads();
        sbuf[tid] = fmaxf(sbuf[tid], vv);
        __syncthreads();
    }
    float emax = (tid == 0) ? NEGINF : sbuf[tid - 1];
#pragma unroll
    for (int j = 0; j < VPT; j++) {
        int s = tid * VPT + j;
        long o = (long)bh * S_ + s;
        float M = fmaxf(emax, mcs[j]);
        gg[o] = gv[j];
        gM[o] = M;
        gEn[o] = __expf(-(Fc[j] + M));
    }
}

// ---------------- mLSTM attention (tf32 mma, pair-scoped P barrier) ---------
#define VSTR 88
__global__ __launch_bounds__(256) void mlstm_attn_tf32(
    const float* __restrict__ q, const float* __restrict__ k,
    const float* __restrict__ v, const float* __restrict__ gg,
    const float* __restrict__ gM, const float* __restrict__ gEn,
    const float* __restrict__ xinner, const float* __restrict__ xconv,
    const float* __restrict__ norm_w, const float* __restrict__ skip,
    float* __restrict__ hout)
{
    int bh = blockIdx.y;
    int b = bh >> 4, h = bh & 15;
    extern __shared__ float sm[];
    float* Qs  = sm;                 // [64][68] s-major
    float* Ks  = Qs + 64 * 68;       // [64][68] t-major; later H[s][d]
    float* Ps  = Ks + 64 * 68;       // [64][68] s-major
    float* Vs  = Ps + 64 * 68;       // [64][VSTR] t-major (col 64 = ones)
    float* Msv = Vs + 64 * VSTR;     // [64]
    float* esv = Msv + 64;           // [64]  exp(g[t] - Mend)
    float* rsv = esv + 64;           // [64]

    int tid = threadIdx.x;
    int warp = tid >> 5, lane = tid & 31;
    int wm = warp & 3, wn = warp >> 2;
    int g = lane >> 2, tig = lane & 3;
    int srow0 = wm * 16 + g, srow1 = srow0 + 8;

    for (int i = tid; i < 64 * (VSTR - 64); i += 256) {
        int t = i / (VSTR - 64), c = i % (VSTR - 64);
        Vs[t * VSTR + 64 + c] = (c == 0) ? 1.0f : 0.0f;
    }

    for (int rep = 0; rep < 2; rep++) {
        int qt = rep ? (31 - (int)blockIdx.x) : (int)blockIdx.x;
        int tok0 = b * S_ + qt * 64;

        __syncthreads();
#pragma unroll
        for (int i = 0; i < 4; i++) {
            int c = tid + i * 256; int s = c >> 4, d0 = (c & 15) * 4;
            float4 qv = *(const float4*)&q[(long)(tok0 + s) * INNER_ + h * DH_ + d0];
            float4 o = {tfstore(qv.x), tfstore(qv.y), tfstore(qv.z), tfstore(qv.w)};
            *(float4*)&Qs[s * 68 + d0] = o;
        }
        if (tid < 64) Msv[tid] = gM[(long)bh * S_ + qt * 64 + tid];
        __syncthreads();
        float Mi0 = Msv[srow0], Mi1 = Msv[srow1];

        uint32_t qf[8][4];
#pragma unroll
        for (int k08 = 0; k08 < 8; k08++) {
            int k0 = k08 * 8;
            qf[k08][0] = __float_as_uint(Qs[srow0 * 68 + k0 + tig]);
            qf[k08][1] = __float_as_uint(Qs[srow1 * 68 + k0 + tig]);
            qf[k08][2] = __float_as_uint(Qs[srow0 * 68 + k0 + tig + 4]);
            qf[k08][3] = __float_as_uint(Qs[srow1 * 68 + k0 + tig + 4]);
        }

        float acc[5][4];
#pragma unroll
        for (int nt = 0; nt < 5; nt++)
#pragma unroll
            for (int i = 0; i < 4; i++) acc[nt][i] = 0.f;

        for (int kt = 0; kt <= qt; kt++) {
            __syncthreads();
            int ktok = b * S_ + kt * 64;
            float Mend = gM[(long)bh * S_ + kt * 64 + 63];
#pragma unroll
            for (int i = 0; i < 4; i++) {
                int c = tid + i * 256; int t = c >> 4, d0 = (c & 15) * 4;
                float4 kv = *(const float4*)&k[(long)(ktok + t) * INNER_ + h * DH_ + d0];
                float4 vv = *(const float4*)&v[(long)(ktok + t) * INNER_ + h * DH_ + d0];
                float4 ko = {tfstore(kv.x), tfstore(kv.y), tfstore(kv.z), tfstore(kv.w)};
                float4 vo = {tfstore(vv.x), tfstore(vv.y), tfstore(vv.z), tfstore(vv.w)};
                *(float4*)&Ks[t * 68 + d0] = ko;
                *(float4*)&Vs[t * VSTR + d0] = vo;
            }
            if (tid < 64)
                esv[tid] = __expf(gg[(long)bh * S_ + kt * 64 + tid] - Mend);
            __syncthreads();

            float p[4][4];
#pragma unroll
            for (int nt = 0; nt < 4; nt++)
#pragma unroll
                for (int i = 0; i < 4; i++) p[nt][i] = 0.f;
#pragma unroll
            for (int k08 = 0; k08 < 8; k08++) {
                int k0 = k08 * 8;
#pragma unroll
                for (int nt = 0; nt < 4; nt++) {
                    int t = wn * 32 + nt * 8 + g;
                    uint32_t b0 = __float_as_uint(Ks[t * 68 + k0 + tig]);
                    uint32_t b1 = __float_as_uint(Ks[t * 68 + k0 + tig + 4]);
                    mma8(p[nt], qf[k08], b0, b1);
                }
            }

            float fr0 = 0.125f * __expf(Mend - Mi0);
            float fr1 = 0.125f * __expf(Mend - Mi1);
            bool diag = (kt == qt);
#pragma unroll
            for (int nt = 0; nt < 4; nt++) {
                int c0c = wn * 32 + nt * 8 + tig * 2;
                float ev0 = esv[c0c], ev1 = esv[c0c + 1];
                float e00 = (diag && c0c     > srow0) ? 0.f : p[nt][0] * fr0 * ev0;
                float e01 = (diag && c0c + 1 > srow0) ? 0.f : p[nt][1] * fr0 * ev1;
                float e10 = (diag && c0c     > srow1) ? 0.f : p[nt][2] * fr1 * ev0;
                float e11 = (diag && c0c + 1 > srow1) ? 0.f : p[nt][3] * fr1 * ev1;
                Ps[srow0 * 68 + c0c]     = tfstore(e00);
                Ps[srow0 * 68 + c0c + 1] = tfstore(e01);
                Ps[srow1 * 68 + c0c]     = tfstore(e10);
                Ps[srow1 * 68 + c0c + 1] = tfstore(e11);
            }
            // P visibility only needed within the wm-pair (wn=0 and wn=1 warps)
            asm volatile("bar.sync %0, 64;" :: "r"(wm + 1) : "memory");

#pragma unroll
            for (int k08 = 0; k08 < 8; k08++) {
                int k0 = k08 * 8;
                uint32_t af[4];
                af[0] = __float_as_uint(Ps[srow0 * 68 + k0 + tig]);
                af[1] = __float_as_uint(Ps[srow1 * 68 + k0 + tig]);
                af[2] = __float_as_uint(Ps[srow0 * 68 + k0 + tig + 4]);
                af[3] = __float_as_uint(Ps[srow1 * 68 + k0 + tig + 4]);
#pragma unroll
                for (int nt = 0; nt < 5; nt++) {
                    int d = wn * 40 + nt * 8 + g;
                    uint32_t b0 = __float_as_uint(Vs[(k0 + tig) * VSTR + d]);
                    uint32_t b1 = __float_as_uint(Vs[(k0 + tig + 4) * VSTR + d]);
                    mma8(acc[nt], af, b0, b1);
                }
            }
        }
        __syncthreads();

#pragma unroll
        for (int nt = 0; nt < 5; nt++) {
            int dcol = wn * 40 + nt * 8 + tig * 2;
            if (dcol < 64) {
                Ks[srow0 * 68 + dcol]     = acc[nt][0];
                Ks[srow0 * 68 + dcol + 1] = acc[nt][1];
                Ks[srow1 * 68 + dcol]     = acc[nt][2];
                Ks[srow1 * 68 + dcol + 1] = acc[nt][3];
            } else if (dcol == 64) {
                rsv[srow0] = acc[nt][0];
                rsv[srow1] = acc[nt][2];
            }
        }
        __syncthreads();

        // epilogue (vectorized global traffic)
        int r2 = tid >> 2, qd = tid & 3;
        float n = fmaxf(fabsf(rsv[r2]), gEn[(long)bh * S_ + qt * 64 + r2]);
        float inv = 1.f / (n + EPS_);
        float hv[16];
        float ss = 0.f;
#pragma unroll
        for (int u = 0; u < 16; u++) {
            hv[u] = Ks[r2 * 68 + qd * 16 + u] * inv;
            ss += hv[u] * hv[u];
        }
        Qs[r2 * 4 + qd] = ss;
        __syncthreads();
        float sumsq = Qs[r2 * 4 + 0] + Qs[r2 * 4 + 1] + Qs[r2 * 4 + 2] + Qs[r2 * 4 + 3];
        float rrms = rsqrtf(sumsq * (1.f / 64.f) + NORM_EPS_);
        int token = tok0 + r2;
        int cbase = h * DH_ + qd * 16;
#pragma unroll
        for (int u4 = 0; u4 < 4; u4++) {
            int c = cbase + u4 * 4;
            float4 nw = *(const float4*)&norm_w[c];
            float4 sk = *(const float4*)&skip[c];
            float4 xc = *(const float4*)&xconv[(long)token * INNER_ + c];
            float4 zz = *(const float4*)&xinner[(long)token * I2_ + INNER_ + c];
            float4 o;
            o.x = (hv[u4*4+0] * rrms * (1.f + nw.x) + sk.x * xc.x) * silu_f(zz.x);
            o.y = (hv[u4*4+1] * rrms * (1.f + nw.y) + sk.y * xc.y) * silu_f(zz.y);
            o.z = (hv[u4*4+2] * rrms * (1.f + nw.z) + sk.z * xc.z) * silu_f(zz.z);
            o.w = (hv[u4*4+3] * rrms * (1.f + nw.w) + sk.w * xc.w) * silu_f(zz.w);
            *(float4*)&hout[(long)token * INNER_ + c] = o;
        }
    }
}

// ---------------------------------------------------------------------------
extern "C" void kernel_launch(void* const* d_in, const int* in_sizes, int n_in,
                              void* d_out, int out_size)
{
    const float* x      = (const float*)d_in[0];
    const float* W_up   = (const float*)d_in[1];
    const float* W_q    = (const float*)d_in[2];
    const float* W_k    = (const float*)d_in[3];
    const float* W_v    = (const float*)d_in[4];
    const float* conv_w = (const float*)d_in[5];
    const float* conv_b = (const float*)d_in[6];
    const float* W_if   = (const float*)d_in[7];
    const float* b_if   = (const float*)d_in[8];
    const float* norm_w = (const float*)d_in[9];
    const float* skip   = (const float*)d_in[10];
    const float* W_down = (const float*)d_in[11];
    float* out = (float*)d_out;

    float *xinner, *xconv, *qp, *kp, *vp, *ifpart, *ifp, *gv, *Mv, *env, *hout;
    cudaGetSymbolAddress((void**)&xinner, g_xinner);
    cudaGetSymbolAddress((void**)&xconv,  g_xconv);
    cudaGetSymbolAddress((void**)&qp,     g_q);
    cudaGetSymbolAddress((void**)&kp,     g_k);
    cudaGetSymbolAddress((void**)&vp,     g_v);
    cudaGetSymbolAddress((void**)&ifpart, g_ifpart);
    cudaGetSymbolAddress((void**)&ifp,    g_if);
    cudaGetSymbolAddress((void**)&gv,     g_gv);
    cudaGetSymbolAddress((void**)&Mv,     g_Mv);
    cudaGetSymbolAddress((void**)&env,    g_env);
    cudaGetSymbolAddress((void**)&hout,   g_hout);

    const int ATTN_SMEM = (3 * 64 * 68 + 64 * VSTR + 192) * (int)sizeof(float);
    cudaFuncSetAttribute(mlstm_attn_tf32,
                         cudaFuncAttributeMaxDynamicSharedMemorySize, ATTN_SMEM);
    const int QKV_SMEM = 3 * 64 * 68 * (int)sizeof(float);
    cudaFuncSetAttribute(qkv_kernel,
                         cudaFuncAttributeMaxDynamicSharedMemorySize, QKV_SMEM);

    gemm_nt_tf32<<<dim3(I2_ / 128, T_ / 128), 256>>>(x, W_up, xinner, T_, I2_, DIM_);
    conv_silu_kernel<<<(T_ / 2 * 256) / 256, 256>>>(xinner, conv_w, conv_b, xconv);
    qkv_kernel<<<dim3(T_ / 64, NH_, 2), 256, QKV_SMEM>>>(
        xconv, xinner, W_q, W_k, W_v, qp, kp, vp);
    ifgate_partial_kernel<<<dim3(T_ / 128, IFSPLIT), 256>>>(qp, kp, vp, W_if, ifpart);
    ifreduce_kernel<<<(T_ * 32 / 4) / 256, 256>>>(ifpart, b_if, ifp);
    gate_scan_kernel<<<B_ * NH_, 256>>>(ifp, gv, Mv, env);
    mlstm_attn_tf32<<<dim3(S_ / 128, B_ * NH_), 256, ATTN_SMEM>>>(
        qp, kp, vp, gv, Mv, env, xinner, xconv, norm_w, skip, hout);
    gemm_nt_tf32<<<dim3(DIM_ / 128, T_ / 128), 256>>>(hout, W_down, out, T_, DIM_, INNER_);
}

// round 15
// speedup vs baseline: 1.0403x; 1.0072x over previous
#include <cuda_runtime.h>
#include <cuda_bf16.h>
#include <cstdint>

#define B_   2
#define S_   2048
#define T_   4096          // B*S
#define DIM_ 512
#define INNER_ 1024
#define I2_  2048
#define NH_  16
#define DH_  64
#define KSZ_ 4
#define EPS_ 5e-5f
#define NORM_EPS_ 1e-6f
#define CAP_ 15.0f
#define IFSPLIT 16

// ---------------- scratch (device globals; no allocation allowed) ----------
__device__ float g_xinner[T_ * I2_];
__device__ float g_xconv [T_ * INNER_];
__device__ float g_q     [T_ * INNER_];
__device__ float g_k     [T_ * INNER_];
__device__ float g_v     [T_ * INNER_];
__device__ float g_ifpart[IFSPLIT * T_ * 32];
__device__ float g_if    [T_ * 32];
__device__ float g_gv    [B_ * NH_ * S_];
__device__ float g_Mv    [B_ * NH_ * S_];
__device__ float g_env   [B_ * NH_ * S_];
__device__ float g_hout  [T_ * INNER_];

// ---------------- tf32 mma helpers -----------------------------------------
__device__ __forceinline__ float tfstore(float x) {
    uint32_t r; asm("cvt.rna.tf32.f32 %0, %1;" : "=r"(r) : "f"(x));
    return __uint_as_float(r);
}
__device__ __forceinline__ void mma8(float* c, const uint32_t* a,
                                     uint32_t b0, uint32_t b1) {
    asm volatile(
        "mma.sync.aligned.m16n8k8.row.col.f32.tf32.tf32.f32 "
        "{%0,%1,%2,%3}, {%4,%5,%6,%7}, {%8,%9}, {%0,%1,%2,%3};"
        : "+f"(c[0]), "+f"(c[1]), "+f"(c[2]), "+f"(c[3])
        : "r"(a[0]), "r"(a[1]), "r"(a[2]), "r"(a[3]), "r"(b0), "r"(b1));
}

__device__ __forceinline__ float silu_f(float z) {
    return z / (1.f + __expf(-z));
}

// ---------------- tf32 NT GEMM, double-buffered (BN=128) --------------------
__global__ __launch_bounds__(256) void gemm_nt_tf32(
    const float* __restrict__ A, const float* __restrict__ Bm,
    float* __restrict__ C, int M, int N, int K)
{
    __shared__ float As[2][16][136];
    __shared__ float Bs[2][16][136];
    int bm = blockIdx.y * 128, bn = blockIdx.x * 128;
    int tid = threadIdx.x;
    int warp = tid >> 5, lane = tid & 31;
    int wm = warp & 3;
    int wn = warp >> 2;
    int g = lane >> 2, tig = lane & 3;
    float acc[2][8][4];
#pragma unroll
    for (int mt = 0; mt < 2; mt++)
#pragma unroll
        for (int nt = 0; nt < 8; nt++)
#pragma unroll
            for (int i = 0; i < 4; i++) acc[mt][nt][i] = 0.f;

    int r = tid >> 1, ks = (tid & 1) * 8;
    const float* Ag = A + (long)(bm + r) * K + ks;
    const float* Bg = Bm + (long)(bn + r) * K + ks;

    // prologue: fill buffer 0
    float4 av0 = *(const float4*)(Ag);
    float4 av1 = *(const float4*)(Ag + 4);
    float4 bv0 = *(const float4*)(Bg);
    float4 bv1 = *(const float4*)(Bg + 4);
    As[0][ks + 0][r] = tfstore(av0.x); As[0][ks + 1][r] = tfstore(av0.y);
    As[0][ks + 2][r] = tfstore(av0.z); As[0][ks + 3][r] = tfstore(av0.w);
    As[0][ks + 4][r] = tfstore(av1.x); As[0][ks + 5][r] = tfstore(av1.y);
    As[0][ks + 6][r] = tfstore(av1.z); As[0][ks + 7][r] = tfstore(av1.w);
    Bs[0][ks + 0][r] = tfstore(bv0.x); Bs[0][ks + 1][r] = tfstore(bv0.y);
    Bs[0][ks + 2][r] = tfstore(bv0.z); Bs[0][ks + 3][r] = tfstore(bv0.w);
    Bs[0][ks + 4][r] = tfstore(bv1.x); Bs[0][ks + 5][r] = tfstore(bv1.y);
    Bs[0][ks + 6][r] = tfstore(bv1.z); Bs[0][ks + 7][r] = tfstore(bv1.w);
    __syncthreads();

    int pb = 0;
    for (int k0 = 0; k0 < K; k0 += 16) {
        bool more = (k0 + 16 < K);
        if (more) {
            av0 = *(const float4*)(Ag + k0 + 16);
            av1 = *(const float4*)(Ag + k0 + 20);
            bv0 = *(const float4*)(Bg + k0 + 16);
            bv1 = *(const float4*)(Bg + k0 + 20);
        }
#pragma unroll
        for (int kk = 0; kk < 16; kk += 8) {
            uint32_t af[2][4];
#pragma unroll
            for (int mt = 0; mt < 2; mt++) {
                int row = wm * 32 + mt * 16;
                af[mt][0] = __float_as_uint(As[pb][kk + tig][row + g]);
                af[mt][1] = __float_as_uint(As[pb][kk + tig][row + g + 8]);
                af[mt][2] = __float_as_uint(As[pb][kk + tig + 4][row + g]);
                af[mt][3] = __float_as_uint(As[pb][kk + tig + 4][row + g + 8]);
            }
#pragma unroll
            for (int nt = 0; nt < 8; nt++) {
                int col = wn * 64 + nt * 8 + g;
                uint32_t b0 = __float_as_uint(Bs[pb][kk + tig][col]);
                uint32_t b1 = __float_as_uint(Bs[pb][kk + tig + 4][col]);
                mma8(acc[0][nt], af[0], b0, b1);
                mma8(acc[1][nt], af[1], b0, b1);
            }
        }
        if (more) {
            int nb = pb ^ 1;
            As[nb][ks + 0][r] = tfstore(av0.x); As[nb][ks + 1][r] = tfstore(av0.y);
            As[nb][ks + 2][r] = tfstore(av0.z); As[nb][ks + 3][r] = tfstore(av0.w);
            As[nb][ks + 4][r] = tfstore(av1.x); As[nb][ks + 5][r] = tfstore(av1.y);
            As[nb][ks + 6][r] = tfstore(av1.z); As[nb][ks + 7][r] = tfstore(av1.w);
            Bs[nb][ks + 0][r] = tfstore(bv0.x); Bs[nb][ks + 1][r] = tfstore(bv0.y);
            Bs[nb][ks + 2][r] = tfstore(bv0.z); Bs[nb][ks + 3][r] = tfstore(bv0.w);
            Bs[nb][ks + 4][r] = tfstore(bv1.x); Bs[nb][ks + 5][r] = tfstore(bv1.y);
            Bs[nb][ks + 6][r] = tfstore(bv1.z); Bs[nb][ks + 7][r] = tfstore(bv1.w);
            __syncthreads();
            pb = nb;
        }
    }
#pragma unroll
    for (int mt = 0; mt < 2; mt++)
#pragma unroll
        for (int nt = 0; nt < 8; nt++) {
            int row = bm + wm * 32 + mt * 16 + g;
            int col = bn + wn * 64 + nt * 8 + tig * 2;
            C[(long)row * N + col]       = acc[mt][nt][0];
            C[(long)row * N + col + 1]   = acc[mt][nt][1];
            C[(long)(row + 8) * N + col]     = acc[mt][nt][2];
            C[(long)(row + 8) * N + col + 1] = acc[mt][nt][3];
        }
}

// ---------------- causal conv1d (KSZ=4) + SiLU, float4, 2 tokens/thread -----
__global__ __launch_bounds__(256) void conv_silu_kernel(
    const float* __restrict__ xinner, const float* __restrict__ cw,
    const float* __restrict__ cb, float* __restrict__ xconv)
{
    int idx = blockIdx.x * 256 + threadIdx.x;
    int c4 = (idx & 255) * 4;
    int tp = idx >> 8;
    int s0 = (tp << 1) & (S_ - 1);
    int b = tp >> 10;
    float4 w0 = *(const float4*)&cw[(c4 + 0) * KSZ_];
    float4 w1 = *(const float4*)&cw[(c4 + 1) * KSZ_];
    float4 w2 = *(const float4*)&cw[(c4 + 2) * KSZ_];
    float4 w3 = *(const float4*)&cw[(c4 + 3) * KSZ_];
    float4 bv = *(const float4*)&cb[c4];
    const float* wj0 = (const float*)&w0;
    const float* wj1 = (const float*)&w1;
    const float* wj2 = (const float*)&w2;
    const float* wj3 = (const float*)&w3;

    float4 xr[5];
#pragma unroll
    for (int r = 0; r < 5; r++) {
        int sp = s0 - 3 + r;
        if (sp >= 0)
            xr[r] = *(const float4*)&xinner[(long)(b * S_ + sp) * I2_ + c4];
        else
            xr[r] = make_float4(0.f, 0.f, 0.f, 0.f);
    }
    long obase = (long)(b * S_ + s0) * INNER_ + c4;
#pragma unroll
    for (int t = 0; t < 2; t++) {
        float a0 = bv.x, a1 = bv.y, a2 = bv.z, a3 = bv.w;
#pragma unroll
        for (int j = 0; j < KSZ_; j++) {
            float4 xv = xr[t + j];
            a0 += xv.x * wj0[j];
            a1 += xv.y * wj1[j];
            a2 += xv.z * wj2[j];
            a3 += xv.w * wj3[j];
        }
        float4 o;
        o.x = silu_f(a0); o.y = silu_f(a1); o.z = silu_f(a2); o.w = silu_f(a3);
        *(float4*)&xconv[obase + (long)t * INNER_] = o;
    }
}

// ---------------- per-head projections: z=0 -> q,k from xconv; z=1 -> v -----
__global__ __launch_bounds__(256) void qkv_kernel(
    const float* __restrict__ xconv, const float* __restrict__ xinner,
    const float* __restrict__ Wq, const float* __restrict__ Wk,
    const float* __restrict__ Wv,
    float* __restrict__ q, float* __restrict__ k, float* __restrict__ v)
{
    int tt = blockIdx.x;
    int h  = blockIdx.y;
    int z  = blockIdx.z;

    extern __shared__ float dsm[];
    float* Xs = dsm;
    float* Wa = Xs + 64 * 68;
    float* Wb = Wa + 64 * 68;

    const float* src = z ? xinner : xconv;
    int srcStride = z ? I2_ : INNER_;
    const float* W1 = z ? Wv : Wq;

    int tid = threadIdx.x, tx = tid & 15, ty = tid >> 4;
    int tok0 = tt * 64;
#pragma unroll
    for (int i = 0; i < 4; i++) {
        int c = tid + i * 256;
        int s = c >> 4, d0 = (c & 15) * 4;
        float4 xv = *(const float4*)&src[(long)(tok0 + s) * srcStride + h * DH_ + d0];
        float4 wv = *(const float4*)&W1[h * DH_ * DH_ + s * DH_ + d0];
        Xs[(d0 + 0) * 68 + s] = xv.x; Xs[(d0 + 1) * 68 + s] = xv.y;
        Xs[(d0 + 2) * 68 + s] = xv.z; Xs[(d0 + 3) * 68 + s] = xv.w;
        Wa[(d0 + 0) * 68 + s] = wv.x; Wa[(d0 + 1) * 68 + s] = wv.y;
        Wa[(d0 + 2) * 68 + s] = wv.z; Wa[(d0 + 3) * 68 + s] = wv.w;
        if (z == 0) {
            float4 wk = *(const float4*)&Wk[h * DH_ * DH_ + s * DH_ + d0];
            Wb[(d0 + 0) * 68 + s] = wk.x; Wb[(d0 + 1) * 68 + s] = wk.y;
            Wb[(d0 + 2) * 68 + s] = wk.z; Wb[(d0 + 3) * 68 + s] = wk.w;
        }
    }
    __syncthreads();

    if (z == 0) {
        float accq[4][4], acck[4][4];
#pragma unroll
        for (int i = 0; i < 4; i++)
#pragma unroll
            for (int j = 0; j < 4; j++) { accq[i][j] = 0.f; acck[i][j] = 0.f; }
#pragma unroll 8
        for (int d = 0; d < 64; d++) {
            float4 a = *(const float4*)&Xs[d * 68 + ty * 4];
            float4 bq = *(const float4*)&Wa[d * 68 + tx * 4];
            float4 bk = *(const float4*)&Wb[d * 68 + tx * 4];
            float av[4] = {a.x,a.y,a.z,a.w};
            float bqv[4] = {bq.x,bq.y,bq.z,bq.w};
            float bkv[4] = {bk.x,bk.y,bk.z,bk.w};
#pragma unroll
            for (int i = 0; i < 4; i++)
#pragma unroll
                for (int j = 0; j < 4; j++) {
                    accq[i][j] += av[i] * bqv[j];
                    acck[i][j] += av[i] * bkv[j];
                }
        }
#pragma unroll
        for (int i = 0; i < 4; i++) {
            float4 oq = {accq[i][0],accq[i][1],accq[i][2],accq[i][3]};
            float4 ok = {acck[i][0],acck[i][1],acck[i][2],acck[i][3]};
            long off = (long)(tok0 + ty * 4 + i) * INNER_ + h * DH_ + tx * 4;
            *(float4*)&q[off] = oq;
            *(float4*)&k[off] = ok;
        }
    } else {
        float accv[4][4];
#pragma unroll
        for (int i = 0; i < 4; i++)
#pragma unroll
            for (int j = 0; j < 4; j++) accv[i][j] = 0.f;
#pragma unroll 16
        for (int d = 0; d < 64; d++) {
            float4 a = *(const float4*)&Xs[d * 68 + ty * 4];
            float4 b = *(const float4*)&Wa[d * 68 + tx * 4];
            float av[4] = {a.x,a.y,a.z,a.w};
            float bv[4] = {b.x,b.y,b.z,b.w};
#pragma unroll
            for (int i = 0; i < 4; i++)
#pragma unroll
                for (int j = 0; j < 4; j++) accv[i][j] += av[i] * bv[j];
        }
#pragma unroll
        for (int i = 0; i < 4; i++) {
            float4 o = {accv[i][0],accv[i][1],accv[i][2],accv[i][3]};
            *(float4*)&v[(long)(tok0 + ty * 4 + i) * INNER_ + h * DH_ + tx * 4] = o;
        }
    }
}

// ---------------- i/f gate GEMM, split-K partials (prefetched) --------------
__global__ __launch_bounds__(256) void ifgate_partial_kernel(
    const float* __restrict__ q, const float* __restrict__ k,
    const float* __restrict__ v, const float* __restrict__ Wif,
    float* __restrict__ part)
{
    int tt = blockIdx.x;
    int z  = blockIdx.y;
    __shared__ float As[32][132];
    __shared__ float Ws[32][36];
    int tid = threadIdx.x;
    int ty = tid >> 3;
    int tx = tid & 7;
    int tok0 = tt * 128;
    float acc[4][4];
#pragma unroll
    for (int i = 0; i < 4; i++)
#pragma unroll
        for (int j = 0; j < 4; j++) acc[i][j] = 0.f;

    int c0 = z * 6;
    int sA = tid >> 3, e4A = (tid & 7) * 4;   // As fill coords (per i-step add 32 rows)
    int gW = tid >> 3, e4W = (tid & 7) * 4;

    // prefetch chunk 0
    float4 xreg[4];
    float4 wreg;
    {
        int e0 = c0 * 32;
        const float* src = (e0 < 1024) ? q : (e0 < 2048) ? k : v;
        int ec = e0 & 1023;
#pragma unroll
        for (int i = 0; i < 4; i++)
            xreg[i] = *(const float4*)&q[0];   // placeholder overwritten below
#pragma unroll
        for (int i = 0; i < 4; i++) {
            int s = sA + i * 32;
            xreg[i] = *(const float4*)&src[(long)(tok0 + s) * INNER_ + ec + e4A];
        }
        wreg = *(const float4*)&Wif[(long)gW * 3072 + e0 + e4W];
    }

    for (int cc = 0; cc < 6; cc++) {
        __syncthreads();
#pragma unroll
        for (int i = 0; i < 4; i++) {
            int s = sA + i * 32;
            As[e4A + 0][s] = xreg[i].x; As[e4A + 1][s] = xreg[i].y;
            As[e4A + 2][s] = xreg[i].z; As[e4A + 3][s] = xreg[i].w;
        }
        Ws[e4W + 0][gW] = wreg.x; Ws[e4W + 1][gW] = wreg.y;
        Ws[e4W + 2][gW] = wreg.z; Ws[e4W + 3][gW] = wreg.w;
        __syncthreads();

        // prefetch next chunk while FFMA loop runs
        if (cc + 1 < 6) {
            int e0 = (c0 + cc + 1) * 32;
            const float* src = (e0 < 1024) ? q : (e0 < 2048) ? k : v;
            int ec = e0 & 1023;
#pragma unroll
            for (int i = 0; i < 4; i++) {
                int s = sA + i * 32;
                xreg[i] = *(const float4*)&src[(long)(tok0 + s) * INNER_ + ec + e4A];
            }
            wreg = *(const float4*)&Wif[(long)gW * 3072 + e0 + e4W];
        }

#pragma unroll 8
        for (int e = 0; e < 32; e++) {
            float4 a = *(const float4*)&As[e][ty * 4];
            float4 b = *(const float4*)&Ws[e][tx * 4];
            float av[4] = {a.x,a.y,a.z,a.w};
            float bv[4] = {b.x,b.y,b.z,b.w};
#pragma unroll
            for (int i = 0; i < 4; i++)
#pragma unroll
                for (int j = 0; j < 4; j++) acc[i][j] += av[i] * bv[j];
        }
    }
#pragma unroll
    for (int i = 0; i < 4; i++) {
        int token = tok0 + ty * 4 + i;
        float4 o = {acc[i][0],acc[i][1],acc[i][2],acc[i][3]};
        *(float4*)&part[((long)z * T_ + token) * 32 + tx * 4] = o;
    }
}

// ---------------- split-K reduce + bias + cap (float4) ----------------------
__global__ __launch_bounds__(256) void ifreduce_kernel(
    const float* __restrict__ part, const float* __restrict__ bif,
    float* __restrict__ ifp)
{
    int idx4 = blockIdx.x * 256 + threadIdx.x;
    int base = idx4 * 4;
    int g4 = base & 31;
    float4 s = {0.f, 0.f, 0.f, 0.f};
#pragma unroll
    for (int z = 0; z < IFSPLIT; z++) {
        float4 p = *(const float4*)&part[(long)z * T_ * 32 + base];
        s.x += p.x; s.y += p.y; s.z += p.z; s.w += p.w;
    }
    float4 bb = *(const float4*)&bif[g4];
    float4 o;
    o.x = CAP_ * tanhf((s.x + bb.x) * (1.0f / CAP_));
    o.y = CAP_ * tanhf((s.y + bb.y) * (1.0f / CAP_));
    o.z = CAP_ * tanhf((s.z + bb.z) * (1.0f / CAP_));
    o.w = CAP_ * tanhf((s.w + bb.w) * (1.0f / CAP_));
    *(float4*)&ifp[base] = o;
}

// ---------------- gate prefix scan per (b,h) --------------------------------
__global__ __launch_bounds__(256) void gate_scan_kernel(
    const float* __restrict__ ifp, float* __restrict__ gg,
    float* __restrict__ gM, float* __restrict__ gEn)
{
    const float NEGINF = -3.0e38f;
    int bh = blockIdx.x;
    int b = bh / NH_, h = bh % NH_;
    int tid = threadIdx.x;
    __shared__ float sbuf[256];
    const int VPT = 8;
    float li[VPT], cs[VPT];
    float csum = 0.f;
#pragma unroll
    for (int j = 0; j < VPT; j++) {
        int s = tid * VPT + j;
        long base = (long)(b * S_ + s) * 32;
        float f = ifp[base + 16 + h];
        li[j] = ifp[base + h];
        float ls = fminf(f, 0.f) - log1pf(__expf(-fabsf(f)));
        csum += ls;
        cs[j] = csum;
    }
    sbuf[tid] = csum; __syncthreads();
    for (int off = 1; off < 256; off <<= 1) {
        float vv = (tid >= off) ? sbuf[tid - off] : 0.f;
        __syncthreads();
        sbuf[tid] += vv;
        __syncthreads();
    }
    float excl = sbuf[tid] - csum;
    float Fc[VPT], gv[VPT], mcs[VPT];
    float mx = NEGINF;
#pragma unroll
    for (int j = 0; j < VPT; j++) {
        Fc[j] = excl + cs[j];
        gv[j] = li[j] - Fc[j];
        mx = fmaxf(mx, gv[j]);
        mcs[j] = mx;
    }
    __syncthreads();
    sbuf[tid] = mx; __syncthreads();
    for (int off = 1; off < 256; off <<= 1) {
        float vv = (tid >= off) ? sbuf[tid - off] : NEGINF;
        __syncthreads();
        sbuf[tid] = fmaxf(sbuf[tid], vv);
        __syncthreads();
    }
    float emax = (tid == 0) ? NEGINF : sbuf[tid - 1];
#pragma unroll
    for (int j = 0; j < VPT; j++) {
        int s = tid * VPT + j;
        long o = (long)bh * S_ + s;
        float M = fmaxf(emax, mcs[j]);
        gg[o] = gv[j];
        gM[o] = M;
        gEn[o] = __expf(-(Fc[j] + M));
    }
}

// ---------------- mLSTM attention (tf32 mma, pair-scoped P barrier) ---------
#define VSTR 88
__global__ __launch_bounds__(256) void mlstm_attn_tf32(
    const float* __restrict__ q, const float* __restrict__ k,
    const float* __restrict__ v, const float* __restrict__ gg,
    const float* __restrict__ gM, const float* __restrict__ gEn,
    const float* __restrict__ xinner, const float* __restrict__ xconv,
    const float* __restrict__ norm_w, const float* __restrict__ skip,
    float* __restrict__ hout)
{
    int bh = blockIdx.y;
    int b = bh >> 4, h = bh & 15;
    extern __shared__ float sm[];
    float* Qs  = sm;
    float* Ks  = Qs + 64 * 68;
    float* Ps  = Ks + 64 * 68;
    float* Vs  = Ps + 64 * 68;
    float* Msv = Vs + 64 * VSTR;
    float* esv = Msv + 64;
    float* rsv = esv + 64;

    int tid = threadIdx.x;
    int warp = tid >> 5, lane = tid & 31;
    int wm = warp & 3, wn = warp >> 2;
    int g = lane >> 2, tig = lane & 3;
    int srow0 = wm * 16 + g, srow1 = srow0 + 8;

    for (int i = tid; i < 64 * (VSTR - 64); i += 256) {
        int t = i / (VSTR - 64), c = i % (VSTR - 64);
        Vs[t * VSTR + 64 + c] = (c == 0) ? 1.0f : 0.0f;
    }

    for (int rep = 0; rep < 2; rep++) {
        int qt = rep ? (31 - (int)blockIdx.x) : (int)blockIdx.x;
        int tok0 = b * S_ + qt * 64;

        __syncthreads();
#pragma unroll
        for (int i = 0; i < 4; i++) {
            int c = tid + i * 256; int s = c >> 4, d0 = (c & 15) * 4;
            float4 qv = *(const float4*)&q[(long)(tok0 + s) * INNER_ + h * DH_ + d0];
            float4 o = {tfstore(qv.x), tfstore(qv.y), tfstore(qv.z), tfstore(qv.w)};
            *(float4*)&Qs[s * 68 + d0] = o;
        }
        if (tid < 64) Msv[tid] = gM[(long)bh * S_ + qt * 64 + tid];
        __syncthreads();
        float Mi0 = Msv[srow0], Mi1 = Msv[srow1];

        uint32_t qf[8][4];
#pragma unroll
        for (int k08 = 0; k08 < 8; k08++) {
            int k0 = k08 * 8;
            qf[k08][0] = __float_as_uint(Qs[srow0 * 68 + k0 + tig]);
            qf[k08][1] = __float_as_uint(Qs[srow1 * 68 + k0 + tig]);
            qf[k08][2] = __float_as_uint(Qs[srow0 * 68 + k0 + tig + 4]);
            qf[k08][3] = __float_as_uint(Qs[srow1 * 68 + k0 + tig + 4]);
        }

        float acc[5][4];
#pragma unroll
        for (int nt = 0; nt < 5; nt++)
#pragma unroll
            for (int i = 0; i < 4; i++) acc[nt][i] = 0.f;

        for (int kt = 0; kt <= qt; kt++) {
            __syncthreads();
            int ktok = b * S_ + kt * 64;
            float Mend = gM[(long)bh * S_ + kt * 64 + 63];
#pragma unroll
            for (int i = 0; i < 4; i++) {
                int c = tid + i * 256; int t = c >> 4, d0 = (c & 15) * 4;
                float4 kv = *(const float4*)&k[(long)(ktok + t) * INNER_ + h * DH_ + d0];
                float4 vv = *(const float4*)&v[(long)(ktok + t) * INNER_ + h * DH_ + d0];
                float4 ko = {tfstore(kv.x), tfstore(kv.y), tfstore(kv.z), tfstore(kv.w)};
                float4 vo = {tfstore(vv.x), tfstore(vv.y), tfstore(vv.z), tfstore(vv.w)};
                *(float4*)&Ks[t * 68 + d0] = ko;
                *(float4*)&Vs[t * VSTR + d0] = vo;
            }
            if (tid < 64)
                esv[tid] = __expf(gg[(long)bh * S_ + kt * 64 + tid] - Mend);
            __syncthreads();

            float p[4][4];
#pragma unroll
            for (int nt = 0; nt < 4; nt++)
#pragma unroll
                for (int i = 0; i < 4; i++) p[nt][i] = 0.f;
#pragma unroll
            for (int k08 = 0; k08 < 8; k08++) {
                int k0 = k08 * 8;
#pragma unroll
                for (int nt = 0; nt < 4; nt++) {
                    int t = wn * 32 + nt * 8 + g;
                    uint32_t b0 = __float_as_uint(Ks[t * 68 + k0 + tig]);
                    uint32_t b1 = __float_as_uint(Ks[t * 68 + k0 + tig + 4]);
                    mma8(p[nt], qf[k08], b0, b1);
                }
            }

            float fr0 = 0.125f * __expf(Mend - Mi0);
            float fr1 = 0.125f * __expf(Mend - Mi1);
            bool diag = (kt == qt);
#pragma unroll
            for (int nt = 0; nt < 4; nt++) {
                int c0c = wn * 32 + nt * 8 + tig * 2;
                float ev0 = esv[c0c], ev1 = esv[c0c + 1];
                float e00 = (diag && c0c     > srow0) ? 0.f : p[nt][0] * fr0 * ev0;
                float e01 = (diag && c0c + 1 > srow0) ? 0.f : p[nt][1] * fr0 * ev1;
                float e10 = (diag && c0c     > srow1) ? 0.f : p[nt][2] * fr1 * ev0;
                float e11 = (diag && c0c + 1 > srow1) ? 0.f : p[nt][3] * fr1 * ev1;
                Ps[srow0 * 68 + c0c]     = tfstore(e00);
                Ps[srow0 * 68 + c0c + 1] = tfstore(e01);
                Ps[srow1 * 68 + c0c]     = tfstore(e10);
                Ps[srow1 * 68 + c0c + 1] = tfstore(e11);
            }
            asm volatile("bar.sync %0, 64;" :: "r"(wm + 1) : "memory");

#pragma unroll
            for (int k08 = 0; k08 < 8; k08++) {
                int k0 = k08 * 8;
                uint32_t af[4];
                af[0] = __float_as_uint(Ps[srow0 * 68 + k0 + tig]);
                af[1] = __float_as_uint(Ps[srow1 * 68 + k0 + tig]);
                af[2] = __float_as_uint(Ps[srow0 * 68 + k0 + tig + 4]);
                af[3] = __float_as_uint(Ps[srow1 * 68 + k0 + tig + 4]);
#pragma unroll
                for (int nt = 0; nt < 5; nt++) {
                    int d = wn * 40 + nt * 8 + g;
                    uint32_t b0 = __float_as_uint(Vs[(k0 + tig) * VSTR + d]);
                    uint32_t b1 = __float_as_uint(Vs[(k0 + tig + 4) * VSTR + d]);
                    mma8(acc[nt], af, b0, b1);
                }
            }
        }
        __syncthreads();

#pragma unroll
        for (int nt = 0; nt < 5; nt++) {
            int dcol = wn * 40 + nt * 8 + tig * 2;
            if (dcol < 64) {
                Ks[srow0 * 68 + dcol]     = acc[nt][0];
                Ks[srow0 * 68 + dcol + 1] = acc[nt][1];
                Ks[srow1 * 68 + dcol]     = acc[nt][2];
                Ks[srow1 * 68 + dcol + 1] = acc[nt][3];
            } else if (dcol == 64) {
                rsv[srow0] = acc[nt][0];
                rsv[srow1] = acc[nt][2];
            }
        }
        __syncthreads();

        int r2 = tid >> 2, qd = tid & 3;
        float n = fmaxf(fabsf(rsv[r2]), gEn[(long)bh * S_ + qt * 64 + r2]);
        float inv = 1.f / (n + EPS_);
        float hv[16];
        float ss = 0.f;
#pragma unroll
        for (int u = 0; u < 16; u++) {
            hv[u] = Ks[r2 * 68 + qd * 16 + u] * inv;
            ss += hv[u] * hv[u];
        }
        Qs[r2 * 4 + qd] = ss;
        __syncthreads();
        float sumsq = Qs[r2 * 4 + 0] + Qs[r2 * 4 + 1] + Qs[r2 * 4 + 2] + Qs[r2 * 4 + 3];
        float rrms = rsqrtf(sumsq * (1.f / 64.f) + NORM_EPS_);
        int token = tok0 + r2;
        int cbase = h * DH_ + qd * 16;
#pragma unroll
        for (int u4 = 0; u4 < 4; u4++) {
            int c = cbase + u4 * 4;
            float4 nw = *(const float4*)&norm_w[c];
            float4 sk = *(const float4*)&skip[c];
            float4 xc = *(const float4*)&xconv[(long)token * INNER_ + c];
            float4 zz = *(const float4*)&xinner[(long)token * I2_ + INNER_ + c];
            float4 o;
            o.x = (hv[u4*4+0] * rrms * (1.f + nw.x) + sk.x * xc.x) * silu_f(zz.x);
            o.y = (hv[u4*4+1] * rrms * (1.f + nw.y) + sk.y * xc.y) * silu_f(zz.y);
            o.z = (hv[u4*4+2] * rrms * (1.f + nw.z) + sk.z * xc.z) * silu_f(zz.z);
            o.w = (hv[u4*4+3] * rrms * (1.f + nw.w) + sk.w * xc.w) * silu_f(zz.w);
            *(float4*)&hout[(long)token * INNER_ + c] = o;
        }
    }
}

// ---------------------------------------------------------------------------
extern "C" void kernel_launch(void* const* d_in, const int* in_sizes, int n_in,
                              void* d_out, int out_size)
{
    const float* x      = (const float*)d_in[0];
    const float* W_up   = (const float*)d_in[1];
    const float* W_q    = (const float*)d_in[2];
    const float* W_k    = (const float*)d_in[3];
    const float* W_v    = (const float*)d_in[4];
    const float* conv_w = (const float*)d_in[5];
    const float* conv_b = (const float*)d_in[6];
    const float* W_if   = (const float*)d_in[7];
    const float* b_if   = (const float*)d_in[8];
    const float* norm_w = (const float*)d_in[9];
    const float* skip   = (const float*)d_in[10];
    const float* W_down = (const float*)d_in[11];
    float* out = (float*)d_out;

    float *xinner, *xconv, *qp, *kp, *vp, *ifpart, *ifp, *gv, *Mv, *env, *hout;
    cudaGetSymbolAddress((void**)&xinner, g_xinner);
    cudaGetSymbolAddress((void**)&xconv,  g_xconv);
    cudaGetSymbolAddress((void**)&qp,     g_q);
    cudaGetSymbolAddress((void**)&kp,     g_k);
    cudaGetSymbolAddress((void**)&vp,     g_v);
    cudaGetSymbolAddress((void**)&ifpart, g_ifpart);
    cudaGetSymbolAddress((void**)&ifp,    g_if);
    cudaGetSymbolAddress((void**)&gv,     g_gv);
    cudaGetSymbolAddress((void**)&Mv,     g_Mv);
    cudaGetSymbolAddress((void**)&env,    g_env);
    cudaGetSymbolAddress((void**)&hout,   g_hout);

    const int ATTN_SMEM = (3 * 64 * 68 + 64 * VSTR + 192) * (int)sizeof(float);
    cudaFuncSetAttribute(mlstm_attn_tf32,
                         cudaFuncAttributeMaxDynamicSharedMemorySize, ATTN_SMEM);
    const int QKV_SMEM = 3 * 64 * 68 * (int)sizeof(float);
    cudaFuncSetAttribute(qkv_kernel,
                         cudaFuncAttributeMaxDynamicSharedMemorySize, QKV_SMEM);

    gemm_nt_tf32<<<dim3(I2_ / 128, T_ / 128), 256>>>(x, W_up, xinner, T_, I2_, DIM_);
    conv_silu_kernel<<<(T_ / 2 * 256) / 256, 256>>>(xinner, conv_w, conv_b, xconv);
    qkv_kernel<<<dim3(T_ / 64, NH_, 2), 256, QKV_SMEM>>>(
        xconv, xinner, W_q, W_k, W_v, qp, kp, vp);
    ifgate_partial_kernel<<<dim3(T_ / 128, IFSPLIT), 256>>>(qp, kp, vp, W_if, ifpart);
    ifreduce_kernel<<<(T_ * 32 / 4) / 256, 256>>>(ifpart, b_if, ifp);
    gate_scan_kernel<<<B_ * NH_, 256>>>(ifp, gv, Mv, env);
    mlstm_attn_tf32<<<dim3(S_ / 128, B_ * NH_), 256, ATTN_SMEM>>>(
        qp, kp, vp, gv, Mv, env, xinner, xconv, norm_w, skip, hout);
    gemm_nt_tf32<<<dim3(DIM_ / 128, T_ / 128), 256>>>(hout, W_down, out, T_, DIM_, INNER_);
}